// round 15
// baseline (speedup 1.0000x reference)
#include <cuda_runtime.h>
#include <cuda_fp16.h>
#include <cstdint>

#define BATCH 32
#define DIM 1024
#define MLEN 512
#define NTILE 8                /* DIM / 128 */
#define NTRI 36                /* triu tile count */
#define NOFF 28                /* off-diag tile count */
#define TRIU_PER_B 524800      /* 1024*1025/2 */
#define INV2M (1.0f / 1024.0f)
#define NEG2INV (-2.0f / 1024.0f)
#define ALPHA_C 0.4f
#define EPS_C 1e-5f
#define DIAG_V 0.01f           /* (1e-5)^0.4 exactly (fp32) */

#define NCH 32                 /* k-chunks of 16 */
#define INFLIGHT 6
#define RSTRIDE 48             /* smem row stride bytes (LDSM + STS conflict-free) */
#define TILE_B (128 * RSTRIDE) /* 6144 */
#define STAGE_B (2 * TILE_B)   /* 12288: A, B */
#define NSTAGE 8
#define SMEM_MAIN (NSTAGE * STAGE_B)  /* 98304 */

// ---- scratch (no device allocation allowed) -------------------------------
__device__ __half g_h[(size_t)BATCH * DIM * MLEN];
__device__ float g_diag[BATCH * DIM];
__device__ float g_rowsum[BATCH * DIM];
__device__ float g_rmean[BATCH * DIM];
__device__ float g_tot[BATCH];

#define LDSM4(R, ADDR)                                                         \
    asm volatile("ldmatrix.sync.aligned.m8n8.x4.shared.b16 {%0,%1,%2,%3}, [%4];" \
        : "=r"((R)[0]), "=r"((R)[1]), "=r"((R)[2]), "=r"((R)[3]) : "r"(ADDR))

#define MMA_F16(D, A, B0, B1)                                                  \
    asm volatile(                                                              \
        "mma.sync.aligned.m16n8k16.row.col.f32.f16.f16.f32 "                   \
        "{%0,%1,%2,%3},{%4,%5,%6,%7},{%8,%9},{%0,%1,%2,%3};"                   \
        : "+f"((D)[0]), "+f"((D)[1]), "+f"((D)[2]), "+f"((D)[3])               \
        : "r"((A)[0]), "r"((A)[1]), "r"((A)[2]), "r"((A)[3]),                  \
          "r"(B0), "r"(B1))

#define CP16(dst, src)                                                         \
    asm volatile("cp.async.cg.shared.global [%0], [%1], 16;"                   \
                 :: "r"(dst), "l"(src))
#define CP_COMMIT() asm volatile("cp.async.commit_group;" ::: "memory")
#define CP_WAIT(n)  asm volatile("cp.async.wait_group %0;" :: "n"(n) : "memory")

__device__ __forceinline__ uint32_t smem_u32(const void* p) {
    uint32_t a;
    asm("{ .reg .u64 t; cvta.to.shared.u64 t, %1; cvt.u32.u64 %0, t; }"
        : "=r"(a) : "l"(p));
    return a;
}

__device__ __forceinline__ float pow04(float dc) {
    return exp2f(ALPHA_C * __log2f(dc));
}

// one K-chunk of MMAs against stage at (tA, tB); DIAG => fragment skip
template <bool DIAG>
__device__ __forceinline__ void chunk_mma(uint32_t tA, uint32_t tB,
                                          uint32_t aOff, uint32_t bOff,
                                          float (&acc)[4][4][4],
                                          const bool (&skipF)[4][4]) {
    uint32_t bh[8];
    LDSM4(bh,     tB + bOff);
    LDSM4(bh + 4, tB + bOff + 16 * RSTRIDE);
#pragma unroll
    for (int mt = 0; mt < 4; ++mt) {
        uint32_t ah[4];
        LDSM4(ah, tA + aOff + mt * (16 * RSTRIDE));
#pragma unroll
        for (int nt = 0; nt < 4; ++nt) {
            if (DIAG && skipF[mt][nt]) continue;
            uint32_t b0 = bh[(nt >> 1) * 4 + (nt & 1) * 2];
            uint32_t b1 = bh[(nt >> 1) * 4 + (nt & 1) * 2 + 1];
            MMA_F16(acc[mt][nt], ah, b0, b1);
        }
    }
}

// ---------------------------------------------------------------------------
// Kernel 1: fp32 -> fp16 convert, fused diag + rowsum zero. 1 warp/row.
// ---------------------------------------------------------------------------
__global__ void k_half(const float* __restrict__ x) {
    int row  = blockIdx.x * 8 + (threadIdx.x >> 5);
    int lane = threadIdx.x & 31;
    const float4* p = (const float4*)(x + (size_t)row * MLEN);
    __half* ph = g_h + (size_t)row * MLEN;
    float s = 0.f;
#pragma unroll
    for (int it = 0; it < 4; ++it) {
        int idx = lane + 32 * it;
        float4 v = p[idx];
        s += v.x * v.x + v.y * v.y + v.z * v.z + v.w * v.w;
        __half hh[4];
        hh[0] = __float2half(v.x); hh[1] = __float2half(v.y);
        hh[2] = __float2half(v.z); hh[3] = __float2half(v.w);
        *(uint2*)(ph + idx * 4) = *(uint2*)hh;
    }
#pragma unroll
    for (int o = 16; o; o >>= 1) s += __shfl_xor_sync(0xffffffffu, s, o);
    if (lane == 0) {
        g_diag[row]   = s * INV2M;
        g_rowsum[row] = 0.f;
    }
}

// ---------------------------------------------------------------------------
// Kernel 2: fp16 HMMA Gram, cp.async 8-stage ring (6 in flight, issue-before-
// wait), barrier-free tail, diag-last ordering, R7 epilogue. 2 blocks/SM.
// ---------------------------------------------------------------------------
__global__ void __launch_bounds__(256, 2) k_main(float* __restrict__ out) {
    extern __shared__ char S[];
    __shared__ float rAcc[128], cAcc[128];

    int tid = threadIdx.x, wid = tid >> 5, lane = tid & 31;
    int g   = lane >> 2, tg = lane & 3;
    int wm  = wid >> 2, wn = wid & 3;

    // diag-last ordering: [0, 32*28) off-diag, [896, 1152) diag
    int blk = blockIdx.x;
    int b, ti, tj;
    if (blk < BATCH * NOFF) {
        b = blk / NOFF;
        int idx = blk - b * NOFF;          // 0..27 -> (ti,tj), ti<tj
        ti = 0;
        while (idx >= NTILE - 1 - ti) { idx -= NTILE - 1 - ti; ++ti; }
        tj = ti + 1 + idx;
    } else {
        int d = blk - BATCH * NOFF;
        b  = d >> 3;
        ti = d & 7;
        tj = ti;
    }

    if (tid < 128) { rAcc[tid] = 0.f; cAcc[tid] = 0.f; }

    bool diagT = (ti == tj);
    bool skipF[4][4];
#pragma unroll
    for (int mt = 0; mt < 4; ++mt)
#pragma unroll
        for (int nt = 0; nt < 4; ++nt)
            skipF[mt][nt] = diagT && (wn * 32 + nt * 8 + 7 < wm * 64 + mt * 16);

    // loader: threads 0..127 -> A-tile row, 128..255 -> B-tile row
    int lrow = tid & 127;
    int tsel = tid >> 7;
    size_t rowoff = ((size_t)b * DIM + (size_t)(tsel ? tj : ti) * 128 + lrow) * MLEN;
    const char* srcH = (const char*)(g_h + rowoff);

    uint32_t sbase = smem_u32(S);
    uint32_t dH = sbase + (tsel ? TILE_B : 0) + (uint32_t)lrow * RSTRIDE;

    int rot = (blockIdx.x & 1) << 4;       // odd blocks process chunks 16..31,0..15

    auto issue = [&](int kc, int st) {
        uint32_t o = (uint32_t)st * STAGE_B;
        int go = ((kc + rot) & (NCH - 1)) * 32;   // 16 fp16 = 32 bytes per row
        CP16(dH + o,      srcH + go);
        CP16(dH + o + 16, srcH + go + 16);
        CP_COMMIT();
    };

    uint32_t aOff = (uint32_t)((wm * 64 + ((lane >> 3) & 1) * 8 + (lane & 7)) * RSTRIDE
                               + (lane >> 4) * 16);
    uint32_t bOff = (uint32_t)((wn * 32 + ((lane >> 4) & 1) * 8 + (lane & 7)) * RSTRIDE
                               + ((lane >> 3) & 1) * 16);

    float acc[4][4][4];
#pragma unroll
    for (int i = 0; i < 4; ++i)
#pragma unroll
        for (int j = 0; j < 4; ++j)
#pragma unroll
            for (int k = 0; k < 4; ++k) acc[i][j][k] = 0.f;

    issue(0, 0); issue(1, 1); issue(2, 2);
    issue(3, 3); issue(4, 4); issue(5, 5);

    int st  = 0;            // stage of chunk kc
    int sti = INFLIGHT;     // stage of chunk kc+INFLIGHT

    if (!diagT) {
        // -------- off-diagonal: issue-before-wait body + barrier-free tail ---
#pragma unroll 1
        for (int kc = 0; kc < NCH - INFLIGHT; ++kc) {
            issue(kc + INFLIGHT, sti);     // stage held chunk kc-2: drained
            CP_WAIT(INFLIGHT);             // chunk kc complete
            __syncthreads();
            uint32_t tA = sbase + (uint32_t)st * STAGE_B;
            if (++st == NSTAGE) st = 0;
            if (++sti == NSTAGE) sti = 0;
            chunk_mma<false>(tA, tA + TILE_B, aOff, bOff, acc, skipF);
        }
        CP_WAIT(0);
        __syncthreads();
#pragma unroll 1
        for (int kc = NCH - INFLIGHT; kc < NCH; ++kc) {
            uint32_t tA = sbase + (uint32_t)st * STAGE_B;
            if (++st == NSTAGE) st = 0;
            chunk_mma<false>(tA, tA + TILE_B, aOff, bOff, acc, skipF);
        }
    } else {
        // -------- diagonal: fragment skip ------------------------------------
#pragma unroll 1
        for (int kc = 0; kc < NCH - INFLIGHT; ++kc) {
            issue(kc + INFLIGHT, sti);
            CP_WAIT(INFLIGHT);
            __syncthreads();
            uint32_t tA = sbase + (uint32_t)st * STAGE_B;
            if (++st == NSTAGE) st = 0;
            if (++sti == NSTAGE) sti = 0;
            chunk_mma<true>(tA, tA + TILE_B, aOff, bOff, acc, skipF);
        }
        CP_WAIT(0);
        __syncthreads();
#pragma unroll 1
        for (int kc = NCH - INFLIGHT; kc < NCH; ++kc) {
            uint32_t tA = sbase + (uint32_t)st * STAGE_B;
            if (++st == NSTAGE) st = 0;
            chunk_mma<true>(tA, tA + TILE_B, aOff, bOff, acc, skipF);
        }
    }

    // ---- epilogue (R7 unified, predicated) ----------------------------------
    float diA[8], djB[8];
#pragma unroll
    for (int mt = 0; mt < 4; ++mt) {
        diA[mt * 2 + 0] = g_diag[b * DIM + ti * 128 + wm * 64 + mt * 16 + g];
        diA[mt * 2 + 1] = g_diag[b * DIM + ti * 128 + wm * 64 + mt * 16 + g + 8];
    }
#pragma unroll
    for (int nt = 0; nt < 4; ++nt) {
        djB[nt * 2 + 0] = g_diag[b * DIM + tj * 128 + wn * 32 + nt * 8 + tg * 2];
        djB[nt * 2 + 1] = g_diag[b * DIM + tj * 128 + wn * 32 + nt * 8 + tg * 2 + 1];
    }

    float* outb = out + (size_t)b * TRIU_PER_B;
    float r8[8], c8[8];
#pragma unroll
    for (int k = 0; k < 8; ++k) { r8[k] = 0.f; c8[k] = 0.f; }

#pragma unroll
    for (int mt = 0; mt < 4; ++mt) {
        int gi0 = ti * 128 + wm * 64 + mt * 16 + g;
        int gi1 = gi0 + 8;
        int rb0 = gi0 * DIM - (gi0 * (gi0 - 1)) / 2 - gi0;
        int rb1 = gi1 * DIM - (gi1 * (gi1 - 1)) / 2 - gi1;
#pragma unroll
        for (int nt = 0; nt < 4; ++nt) {
            if (skipF[mt][nt]) continue;
            int gj0 = tj * 128 + wn * 32 + nt * 8 + tg * 2;
            int gj1 = gj0 + 1;
            float v00, v01, v10, v11;
            {
                float dc = fmaxf(fmaf(acc[mt][nt][0], NEG2INV, diA[mt*2] + djB[nt*2]), 0.f) + EPS_C;
                v00 = (gi0 == gj0) ? DIAG_V : pow04(dc);
            }
            {
                float dc = fmaxf(fmaf(acc[mt][nt][1], NEG2INV, diA[mt*2] + djB[nt*2+1]), 0.f) + EPS_C;
                v01 = (gi0 == gj1) ? DIAG_V : pow04(dc);
            }
            {
                float dc = fmaxf(fmaf(acc[mt][nt][2], NEG2INV, diA[mt*2+1] + djB[nt*2]), 0.f) + EPS_C;
                v10 = (gi1 == gj0) ? DIAG_V : pow04(dc);
            }
            {
                float dc = fmaxf(fmaf(acc[mt][nt][3], NEG2INV, diA[mt*2+1] + djB[nt*2+1]), 0.f) + EPS_C;
                v11 = (gi1 == gj1) ? DIAG_V : pow04(dc);
            }
            if (gj0 >= gi0) outb[rb0 + gj0] = v00;
            if (gj1 >= gi0) outb[rb0 + gj1] = v01;
            if (gj0 >= gi1) outb[rb1 + gj0] = v10;
            if (gj1 >= gi1) outb[rb1 + gj1] = v11;
            r8[mt*2+0] += ((gj0 >= gi0) ? v00 : 0.f) + ((gj1 >= gi0) ? v01 : 0.f);
            r8[mt*2+1] += ((gj0 >= gi1) ? v10 : 0.f) + ((gj1 >= gi1) ? v11 : 0.f);
            c8[nt*2+0] += ((gj0 > gi0) ? v00 : 0.f) + ((gj0 > gi1) ? v10 : 0.f);
            c8[nt*2+1] += ((gj1 > gi0) ? v01 : 0.f) + ((gj1 > gi1) ? v11 : 0.f);
        }
    }

    // row partials: reduce over tg (lane bits 0,1)
#pragma unroll
    for (int k = 0; k < 8; ++k) {
        r8[k] += __shfl_xor_sync(0xffffffffu, r8[k], 1);
        r8[k] += __shfl_xor_sync(0xffffffffu, r8[k], 2);
    }
    if (tg == 0) {
#pragma unroll
        for (int k = 0; k < 8; ++k)
            atomicAdd(&rAcc[wm * 64 + (k >> 1) * 16 + g + (k & 1) * 8], r8[k]);
    }
    // col partials: reduce over g (lane bits 2,3,4)
#pragma unroll
    for (int k = 0; k < 8; ++k) {
        c8[k] += __shfl_xor_sync(0xffffffffu, c8[k], 4);
        c8[k] += __shfl_xor_sync(0xffffffffu, c8[k], 8);
        c8[k] += __shfl_xor_sync(0xffffffffu, c8[k], 16);
    }
    if (g == 0) {
#pragma unroll
        for (int k = 0; k < 8; ++k)
            atomicAdd(&cAcc[wn * 32 + (k >> 1) * 8 + tg * 2 + (k & 1)], c8[k]);
    }
    __syncthreads();

    if (tid < 128) {
        atomicAdd(&g_rowsum[b * DIM + ti * 128 + tid], rAcc[tid]);
        atomicAdd(&g_rowsum[b * DIM + tj * 128 + tid], cAcc[tid]);
    }
}

// ---------------------------------------------------------------------------
// Kernel 3: finalize per-batch means
// ---------------------------------------------------------------------------
__global__ void k_means() {
    int b = blockIdx.x, tid = threadIdx.x;
    __shared__ float red[256];
    float s = 0.f;
    for (int i = tid; i < DIM; i += 256) {
        float rs = g_rowsum[b * DIM + i];
        g_rmean[b * DIM + i] = rs * (1.0f / DIM);
        s += rs;
    }
    red[tid] = s;
    __syncthreads();
    for (int o = 128; o; o >>= 1) {
        if (tid < o) red[tid] += red[tid + o];
        __syncthreads();
    }
    if (tid == 0) g_tot[b] = red[0] * (1.0f / ((float)DIM * (float)DIM));
}

// ---------------------------------------------------------------------------
// Kernel 4: flat float4 double-centering, branchless row inversion.
// (sqrtf is correctly rounded -> estimate within 1 of truth; one +-1 fix.)
// ---------------------------------------------------------------------------
__device__ __forceinline__ int rb_of(int i) { return (i * (2 * DIM + 1 - i)) >> 1; }

__global__ void k_center(float* __restrict__ out) {
    int idx = blockIdx.x * blockDim.x + threadIdx.x;   // float4 index
    int b  = idx / (TRIU_PER_B / 4);
    int p  = (idx - b * (TRIU_PER_B / 4)) * 4;
    float arg = (float)(4198401 - 8 * p);
    int i = (int)((2049.0f - sqrtf(arg)) * 0.5f);
    i -= (i > 0 && rb_of(i) > p);
    i += (rb_of(i + 1) <= p);

    const float* rm = g_rmean + b * DIM;
    float tt = g_tot[b];
    float* ptr = out + (size_t)b * TRIU_PER_B + p;
    float4 v = *(float4*)ptr;
    float e[4] = {v.x, v.y, v.z, v.w};
    int ii = i;
#pragma unroll
    for (int k = 0; k < 4; ++k) {
        while (rb_of(ii + 1) <= p + k) ++ii;
        int j = p + k - rb_of(ii) + ii;
        e[k] = e[k] - rm[ii] - rm[j] + tt;
    }
    v.x = e[0]; v.y = e[1]; v.z = e[2]; v.w = e[3];
    *(float4*)ptr = v;
}

// ---------------------------------------------------------------------------
extern "C" void kernel_launch(void* const* d_in, const int* in_sizes, int n_in,
                              void* d_out, int out_size) {
    (void)in_sizes; (void)n_in; (void)out_size;
    const float* x = (const float*)d_in[0];
    float* out = (float*)d_out;

    cudaFuncSetAttribute(k_main, cudaFuncAttributeMaxDynamicSharedMemorySize,
                         SMEM_MAIN);

    k_half<<<(BATCH * DIM) / 8, 256>>>(x);
    k_main<<<BATCH * NTRI, 256, SMEM_MAIN>>>(out);
    k_means<<<BATCH, 256>>>();
    k_center<<<(BATCH * TRIU_PER_B / 4) / 256, 256>>>(out);
}

// round 16
// speedup vs baseline: 1.0604x; 1.0604x over previous
#include <cuda_runtime.h>
#include <cuda_fp16.h>
#include <cstdint>

#define BATCH 32
#define DIM 1024
#define MLEN 512
#define NTILE 8                /* DIM / 128 */
#define NTRI 36                /* triu tile count */
#define NOFF 28                /* off-diag tile count */
#define TRIU_PER_B 524800      /* 1024*1025/2 */
#define INV2M (1.0f / 1024.0f)
#define NEG2INV (-2.0f / 1024.0f)
#define ALPHA_C 0.4f
#define EPS_C 1e-5f
#define DIAG_V 0.01f           /* (1e-5)^0.4 exactly (fp32) */

#define NCH 32                 /* k-chunks of 16 */
#define INFLIGHT 5
#define RSTRIDE 48             /* smem row stride bytes (LDSM + STS conflict-free) */
#define TILE_B (128 * RSTRIDE) /* 6144 */
#define STAGE_B (2 * TILE_B)   /* 12288: A, B */
#define NSTAGE 6
#define SMEM_MAIN (NSTAGE * STAGE_B)  /* 73728 */

// ---- scratch (no device allocation allowed) -------------------------------
__device__ __half g_h[(size_t)BATCH * DIM * MLEN];
__device__ float g_diag[BATCH * DIM];
__device__ float g_rowsum[BATCH * DIM];
__device__ float g_rmean[BATCH * DIM];
__device__ float g_tot[BATCH];

#define LDSM4(R, ADDR)                                                         \
    asm volatile("ldmatrix.sync.aligned.m8n8.x4.shared.b16 {%0,%1,%2,%3}, [%4];" \
        : "=r"((R)[0]), "=r"((R)[1]), "=r"((R)[2]), "=r"((R)[3]) : "r"(ADDR))

#define MMA_F16(D, A, B0, B1)                                                  \
    asm volatile(                                                              \
        "mma.sync.aligned.m16n8k16.row.col.f32.f16.f16.f32 "                   \
        "{%0,%1,%2,%3},{%4,%5,%6,%7},{%8,%9},{%0,%1,%2,%3};"                   \
        : "+f"((D)[0]), "+f"((D)[1]), "+f"((D)[2]), "+f"((D)[3])               \
        : "r"((A)[0]), "r"((A)[1]), "r"((A)[2]), "r"((A)[3]),                  \
          "r"(B0), "r"(B1))

#define CP16(dst, src)                                                         \
    asm volatile("cp.async.cg.shared.global [%0], [%1], 16;"                   \
                 :: "r"(dst), "l"(src))
#define CP_COMMIT() asm volatile("cp.async.commit_group;" ::: "memory")
#define CP_WAIT(n)  asm volatile("cp.async.wait_group %0;" :: "n"(n) : "memory")

__device__ __forceinline__ uint32_t smem_u32(const void* p) {
    uint32_t a;
    asm("{ .reg .u64 t; cvta.to.shared.u64 t, %1; cvt.u32.u64 %0, t; }"
        : "=r"(a) : "l"(p));
    return a;
}

__device__ __forceinline__ float pow04(float dc) {
    return exp2f(ALPHA_C * __log2f(dc));
}

// one K-chunk of MMAs against stage at (tA, tB); DIAG => fragment skip
template <bool DIAG>
__device__ __forceinline__ void chunk_mma(uint32_t tA, uint32_t tB,
                                          uint32_t aOff, uint32_t bOff,
                                          float (&acc)[4][4][4],
                                          const bool (&skipF)[4][4]) {
    uint32_t bh[8];
    LDSM4(bh,     tB + bOff);
    LDSM4(bh + 4, tB + bOff + 16 * RSTRIDE);
#pragma unroll
    for (int mt = 0; mt < 4; ++mt) {
        uint32_t ah[4];
        LDSM4(ah, tA + aOff + mt * (16 * RSTRIDE));
#pragma unroll
        for (int nt = 0; nt < 4; ++nt) {
            if (DIAG && skipF[mt][nt]) continue;
            uint32_t b0 = bh[(nt >> 1) * 4 + (nt & 1) * 2];
            uint32_t b1 = bh[(nt >> 1) * 4 + (nt & 1) * 2 + 1];
            MMA_F16(acc[mt][nt], ah, b0, b1);
        }
    }
}

// ---------------------------------------------------------------------------
// Kernel 1: fp32 -> fp16 convert, fused diag + rowsum zero. 1 warp/row.
// ---------------------------------------------------------------------------
__global__ void k_half(const float* __restrict__ x) {
    int row  = blockIdx.x * 8 + (threadIdx.x >> 5);
    int lane = threadIdx.x & 31;
    const float4* p = (const float4*)(x + (size_t)row * MLEN);
    __half* ph = g_h + (size_t)row * MLEN;
    float s = 0.f;
#pragma unroll
    for (int it = 0; it < 4; ++it) {
        int idx = lane + 32 * it;
        float4 v = p[idx];
        s += v.x * v.x + v.y * v.y + v.z * v.z + v.w * v.w;
        __half hh[4];
        hh[0] = __float2half(v.x); hh[1] = __float2half(v.y);
        hh[2] = __float2half(v.z); hh[3] = __float2half(v.w);
        *(uint2*)(ph + idx * 4) = *(uint2*)hh;
    }
#pragma unroll
    for (int o = 16; o; o >>= 1) s += __shfl_xor_sync(0xffffffffu, s, o);
    if (lane == 0) {
        g_diag[row]   = s * INV2M;
        g_rowsum[row] = 0.f;
    }
}

// ---------------------------------------------------------------------------
// Kernel 2: fp16 HMMA Gram, cp.async 6-stage pipeline, barrier-free tail,
// block-parity chunk rotation, diag-last ordering, R7 epilogue. 2 blocks/SM.
// (R14 configuration, byte-identical.)
// ---------------------------------------------------------------------------
__global__ void __launch_bounds__(256, 2) k_main(float* __restrict__ out) {
    extern __shared__ char S[];
    __shared__ float rAcc[128], cAcc[128];

    int tid = threadIdx.x, wid = tid >> 5, lane = tid & 31;
    int g   = lane >> 2, tg = lane & 3;
    int wm  = wid >> 2, wn = wid & 3;

    // diag-last ordering: [0, 32*28) off-diag, [896, 1152) diag
    int blk = blockIdx.x;
    int b, ti, tj;
    if (blk < BATCH * NOFF) {
        b = blk / NOFF;
        int idx = blk - b * NOFF;          // 0..27 -> (ti,tj), ti<tj
        ti = 0;
        while (idx >= NTILE - 1 - ti) { idx -= NTILE - 1 - ti; ++ti; }
        tj = ti + 1 + idx;
    } else {
        int d = blk - BATCH * NOFF;
        b  = d >> 3;
        ti = d & 7;
        tj = ti;
    }

    if (tid < 128) { rAcc[tid] = 0.f; cAcc[tid] = 0.f; }

    bool diagT = (ti == tj);
    bool skipF[4][4];
#pragma unroll
    for (int mt = 0; mt < 4; ++mt)
#pragma unroll
        for (int nt = 0; nt < 4; ++nt)
            skipF[mt][nt] = diagT && (wn * 32 + nt * 8 + 7 < wm * 64 + mt * 16);

    // loader: threads 0..127 -> A-tile row, 128..255 -> B-tile row
    int lrow = tid & 127;
    int tsel = tid >> 7;
    size_t rowoff = ((size_t)b * DIM + (size_t)(tsel ? tj : ti) * 128 + lrow) * MLEN;
    const char* srcH = (const char*)(g_h + rowoff);

    uint32_t sbase = smem_u32(S);
    uint32_t dH = sbase + (tsel ? TILE_B : 0) + (uint32_t)lrow * RSTRIDE;

    int rot = (blockIdx.x & 1) << 4;       // odd blocks process chunks 16..31,0..15

    auto issue = [&](int kc, int st) {
        uint32_t o = (uint32_t)st * STAGE_B;
        int go = ((kc + rot) & (NCH - 1)) * 32;   // 16 fp16 = 32 bytes per row
        CP16(dH + o,      srcH + go);
        CP16(dH + o + 16, srcH + go + 16);
        CP_COMMIT();
    };

    uint32_t aOff = (uint32_t)((wm * 64 + ((lane >> 3) & 1) * 8 + (lane & 7)) * RSTRIDE
                               + (lane >> 4) * 16);
    uint32_t bOff = (uint32_t)((wn * 32 + ((lane >> 4) & 1) * 8 + (lane & 7)) * RSTRIDE
                               + ((lane >> 3) & 1) * 16);

    float acc[4][4][4];
#pragma unroll
    for (int i = 0; i < 4; ++i)
#pragma unroll
        for (int j = 0; j < 4; ++j)
#pragma unroll
            for (int k = 0; k < 4; ++k) acc[i][j][k] = 0.f;

    issue(0, 0); issue(1, 1); issue(2, 2); issue(3, 3); issue(4, 4);

    int st  = 0;            // stage of chunk kc
    int sti = INFLIGHT;     // stage of chunk kc+INFLIGHT

    if (!diagT) {
        // -------- off-diagonal: pipelined body + barrier-free tail -----------
#pragma unroll 1
        for (int kc = 0; kc < NCH - INFLIGHT; ++kc) {
            CP_WAIT(4);
            __syncthreads();
            issue(kc + INFLIGHT, sti);
            uint32_t tA = sbase + (uint32_t)st * STAGE_B;
            if (++st == NSTAGE) st = 0;
            if (++sti == NSTAGE) sti = 0;
            chunk_mma<false>(tA, tA + TILE_B, aOff, bOff, acc, skipF);
        }
        CP_WAIT(0);
        __syncthreads();
#pragma unroll 1
        for (int kc = NCH - INFLIGHT; kc < NCH; ++kc) {
            uint32_t tA = sbase + (uint32_t)st * STAGE_B;
            if (++st == NSTAGE) st = 0;
            chunk_mma<false>(tA, tA + TILE_B, aOff, bOff, acc, skipF);
        }
    } else {
        // -------- diagonal: fragment skip ------------------------------------
#pragma unroll 1
        for (int kc = 0; kc < NCH - INFLIGHT; ++kc) {
            CP_WAIT(4);
            __syncthreads();
            issue(kc + INFLIGHT, sti);
            uint32_t tA = sbase + (uint32_t)st * STAGE_B;
            if (++st == NSTAGE) st = 0;
            if (++sti == NSTAGE) sti = 0;
            chunk_mma<true>(tA, tA + TILE_B, aOff, bOff, acc, skipF);
        }
        CP_WAIT(0);
        __syncthreads();
#pragma unroll 1
        for (int kc = NCH - INFLIGHT; kc < NCH; ++kc) {
            uint32_t tA = sbase + (uint32_t)st * STAGE_B;
            if (++st == NSTAGE) st = 0;
            chunk_mma<true>(tA, tA + TILE_B, aOff, bOff, acc, skipF);
        }
    }

    // ---- epilogue (R7 unified, predicated) ----------------------------------
    float diA[8], djB[8];
#pragma unroll
    for (int mt = 0; mt < 4; ++mt) {
        diA[mt * 2 + 0] = g_diag[b * DIM + ti * 128 + wm * 64 + mt * 16 + g];
        diA[mt * 2 + 1] = g_diag[b * DIM + ti * 128 + wm * 64 + mt * 16 + g + 8];
    }
#pragma unroll
    for (int nt = 0; nt < 4; ++nt) {
        djB[nt * 2 + 0] = g_diag[b * DIM + tj * 128 + wn * 32 + nt * 8 + tg * 2];
        djB[nt * 2 + 1] = g_diag[b * DIM + tj * 128 + wn * 32 + nt * 8 + tg * 2 + 1];
    }

    float* outb = out + (size_t)b * TRIU_PER_B;
    float r8[8], c8[8];
#pragma unroll
    for (int k = 0; k < 8; ++k) { r8[k] = 0.f; c8[k] = 0.f; }

#pragma unroll
    for (int mt = 0; mt < 4; ++mt) {
        int gi0 = ti * 128 + wm * 64 + mt * 16 + g;
        int gi1 = gi0 + 8;
        int rb0 = gi0 * DIM - (gi0 * (gi0 - 1)) / 2 - gi0;
        int rb1 = gi1 * DIM - (gi1 * (gi1 - 1)) / 2 - gi1;
#pragma unroll
        for (int nt = 0; nt < 4; ++nt) {
            if (skipF[mt][nt]) continue;
            int gj0 = tj * 128 + wn * 32 + nt * 8 + tg * 2;
            int gj1 = gj0 + 1;
            float v00, v01, v10, v11;
            {
                float dc = fmaxf(fmaf(acc[mt][nt][0], NEG2INV, diA[mt*2] + djB[nt*2]), 0.f) + EPS_C;
                v00 = (gi0 == gj0) ? DIAG_V : pow04(dc);
            }
            {
                float dc = fmaxf(fmaf(acc[mt][nt][1], NEG2INV, diA[mt*2] + djB[nt*2+1]), 0.f) + EPS_C;
                v01 = (gi0 == gj1) ? DIAG_V : pow04(dc);
            }
            {
                float dc = fmaxf(fmaf(acc[mt][nt][2], NEG2INV, diA[mt*2+1] + djB[nt*2]), 0.f) + EPS_C;
                v10 = (gi1 == gj0) ? DIAG_V : pow04(dc);
            }
            {
                float dc = fmaxf(fmaf(acc[mt][nt][3], NEG2INV, diA[mt*2+1] + djB[nt*2+1]), 0.f) + EPS_C;
                v11 = (gi1 == gj1) ? DIAG_V : pow04(dc);
            }
            if (gj0 >= gi0) outb[rb0 + gj0] = v00;
            if (gj1 >= gi0) outb[rb0 + gj1] = v01;
            if (gj0 >= gi1) outb[rb1 + gj0] = v10;
            if (gj1 >= gi1) outb[rb1 + gj1] = v11;
            r8[mt*2+0] += ((gj0 >= gi0) ? v00 : 0.f) + ((gj1 >= gi0) ? v01 : 0.f);
            r8[mt*2+1] += ((gj0 >= gi1) ? v10 : 0.f) + ((gj1 >= gi1) ? v11 : 0.f);
            c8[nt*2+0] += ((gj0 > gi0) ? v00 : 0.f) + ((gj0 > gi1) ? v10 : 0.f);
            c8[nt*2+1] += ((gj1 > gi0) ? v01 : 0.f) + ((gj1 > gi1) ? v11 : 0.f);
        }
    }

    // row partials: reduce over tg (lane bits 0,1)
#pragma unroll
    for (int k = 0; k < 8; ++k) {
        r8[k] += __shfl_xor_sync(0xffffffffu, r8[k], 1);
        r8[k] += __shfl_xor_sync(0xffffffffu, r8[k], 2);
    }
    if (tg == 0) {
#pragma unroll
        for (int k = 0; k < 8; ++k)
            atomicAdd(&rAcc[wm * 64 + (k >> 1) * 16 + g + (k & 1) * 8], r8[k]);
    }
    // col partials: reduce over g (lane bits 2,3,4)
#pragma unroll
    for (int k = 0; k < 8; ++k) {
        c8[k] += __shfl_xor_sync(0xffffffffu, c8[k], 4);
        c8[k] += __shfl_xor_sync(0xffffffffu, c8[k], 8);
        c8[k] += __shfl_xor_sync(0xffffffffu, c8[k], 16);
    }
    if (g == 0) {
#pragma unroll
        for (int k = 0; k < 8; ++k)
            atomicAdd(&cAcc[wn * 32 + (k >> 1) * 8 + tg * 2 + (k & 1)], c8[k]);
    }
    __syncthreads();

    if (tid < 128) {
        atomicAdd(&g_rowsum[b * DIM + ti * 128 + tid], rAcc[tid]);
        atomicAdd(&g_rowsum[b * DIM + tj * 128 + tid], cAcc[tid]);
    }
}

// ---------------------------------------------------------------------------
// Kernel 3: finalize per-batch means
// ---------------------------------------------------------------------------
__global__ void k_means() {
    int b = blockIdx.x, tid = threadIdx.x;
    __shared__ float red[256];
    float s = 0.f;
    for (int i = tid; i < DIM; i += 256) {
        float rs = g_rowsum[b * DIM + i];
        g_rmean[b * DIM + i] = rs * (1.0f / DIM);
        s += rs;
    }
    red[tid] = s;
    __syncthreads();
    for (int o = 128; o; o >>= 1) {
        if (tid < o) red[tid] += red[tid + o];
        __syncthreads();
    }
    if (tid == 0) g_tot[b] = red[0] * (1.0f / ((float)DIM * (float)DIM));
}

// ---------------------------------------------------------------------------
// Kernel 4: flat float4 double-centering, branchless row inversion +
// single-row fast path (float4 spans one row in ~99% of cases).
// ---------------------------------------------------------------------------
__device__ __forceinline__ int rb_of(int i) { return (i * (2 * DIM + 1 - i)) >> 1; }

__global__ void k_center(float* __restrict__ out) {
    int idx = blockIdx.x * blockDim.x + threadIdx.x;   // float4 index
    int b  = idx / (TRIU_PER_B / 4);
    int p  = (idx - b * (TRIU_PER_B / 4)) * 4;
    float arg = (float)(4198401 - 8 * p);
    int i = (int)((2049.0f - sqrtf(arg)) * 0.5f);
    i -= (i > 0 && rb_of(i) > p);
    i += (rb_of(i + 1) <= p);

    const float* rm = g_rmean + b * DIM;
    float tt = g_tot[b];
    float* ptr = out + (size_t)b * TRIU_PER_B + p;
    float4 v = *(float4*)ptr;
    float e[4] = {v.x, v.y, v.z, v.w};

    int j0 = p - rb_of(i) + i;          // column of first element in row i
    if (j0 + 3 < DIM) {
        // fast path: all 4 elements in row i
        float corr = tt - rm[i];
#pragma unroll
        for (int k = 0; k < 4; ++k)
            e[k] = e[k] + (corr - rm[j0 + k]);
    } else {
        // slow path: float4 crosses a row boundary
        int ii = i;
#pragma unroll
        for (int k = 0; k < 4; ++k) {
            while (rb_of(ii + 1) <= p + k) ++ii;
            int j = p + k - rb_of(ii) + ii;
            e[k] = e[k] - rm[ii] - rm[j] + tt;
        }
    }
    v.x = e[0]; v.y = e[1]; v.z = e[2]; v.w = e[3];
    *(float4*)ptr = v;
}

// ---------------------------------------------------------------------------
extern "C" void kernel_launch(void* const* d_in, const int* in_sizes, int n_in,
                              void* d_out, int out_size) {
    (void)in_sizes; (void)n_in; (void)out_size;
    const float* x = (const float*)d_in[0];
    float* out = (float*)d_out;

    cudaFuncSetAttribute(k_main, cudaFuncAttributeMaxDynamicSharedMemorySize,
                         SMEM_MAIN);

    k_half<<<(BATCH * DIM) / 8, 256>>>(x);
    k_main<<<BATCH * NTRI, 256, SMEM_MAIN>>>(out);
    k_means<<<BATCH, 256>>>();
    k_center<<<(BATCH * TRIU_PER_B / 4) / 256, 256>>>(out);
}